// round 2
// baseline (speedup 1.0000x reference)
#include <cuda_runtime.h>
#include <math.h>
#include <stdint.h>

// Problem dims (fixed by the dataset)
#define T_TOK 8192
#define H_DIM 1024
#define I_DIM 4096
#define S_DIM 128
#define TOPK  16

// ---------------------------------------------------------------------------
// Scratch (static device arrays — no allocation allowed in kernel_launch)
// ---------------------------------------------------------------------------
__device__ float g_h1[(size_t)T_TOK * I_DIM];   // 128 MB: gate proj -> h
__device__ float g_h2[(size_t)T_TOK * I_DIM];   // 128 MB: up proj
__device__ float g_gx[(size_t)T_TOK * S_DIM];   // router gate x logits
__device__ float g_gy[(size_t)T_TOK * S_DIM];   // router gate y logits
__device__ float g_bn[4 * S_DIM];               // [mu_x, inv_x, mu_y, inv_y]
__device__ int   g_ti[(size_t)T_TOK * TOPK];    // selected expert ids
__device__ float g_tw[(size_t)T_TOK * TOPK];    // routing weights (exp of score)

// ---------------------------------------------------------------------------
// Tiled fp32 GEMM:  C[M,N] = A[M,K] @ B[N,K]^T   (both row-major, K-contig)
// 128x128 tile, BK=16, 256 threads, 8x8 micro-tile per thread.
// Assumes M%128==0, N%128==0, K%16==0 (true for all calls here).
// ---------------------------------------------------------------------------
#define BM 128
#define BN 128
#define BK 16
#define SLD (BM + 4)  // padded smem stride to break store bank conflicts

template <bool ACC>
__global__ void __launch_bounds__(256, 2)
gemm_nt(const float* __restrict__ A, const float* __restrict__ B,
        float* __restrict__ C, int M, int N, int K)
{
    __shared__ __align__(16) float As[BK][SLD];
    __shared__ __align__(16) float Bs[BK][SLD];

    const int bm  = blockIdx.y * BM;
    const int bn  = blockIdx.x * BN;
    const int tid = threadIdx.x;
    const int tx  = tid & 15;   // n sub-tile
    const int ty  = tid >> 4;   // m sub-tile

    float acc[8][8];
#pragma unroll
    for (int i = 0; i < 8; i++)
#pragma unroll
        for (int j = 0; j < 8; j++) acc[i][j] = 0.f;

    for (int k0 = 0; k0 < K; k0 += BK) {
#pragma unroll
        for (int p = 0; p < 2; p++) {
            int v   = tid + 256 * p;
            int row = v >> 2;          // 0..127
            int c4  = (v & 3) * 4;     // 0,4,8,12
            float4 a = *(const float4*)(A + (size_t)(bm + row) * K + k0 + c4);
            As[c4 + 0][row] = a.x; As[c4 + 1][row] = a.y;
            As[c4 + 2][row] = a.z; As[c4 + 3][row] = a.w;
            float4 b = *(const float4*)(B + (size_t)(bn + row) * K + k0 + c4);
            Bs[c4 + 0][row] = b.x; Bs[c4 + 1][row] = b.y;
            Bs[c4 + 2][row] = b.z; Bs[c4 + 3][row] = b.w;
        }
        __syncthreads();
#pragma unroll
        for (int kk = 0; kk < BK; kk++) {
            float4 a0 = *(const float4*)&As[kk][ty * 8];
            float4 a1 = *(const float4*)&As[kk][ty * 8 + 4];
            float4 b0 = *(const float4*)&Bs[kk][tx * 8];
            float4 b1 = *(const float4*)&Bs[kk][tx * 8 + 4];
            float ra[8] = {a0.x, a0.y, a0.z, a0.w, a1.x, a1.y, a1.z, a1.w};
            float rb[8] = {b0.x, b0.y, b0.z, b0.w, b1.x, b1.y, b1.z, b1.w};
#pragma unroll
            for (int i = 0; i < 8; i++)
#pragma unroll
                for (int j = 0; j < 8; j++)
                    acc[i][j] = fmaf(ra[i], rb[j], acc[i][j]);
        }
        __syncthreads();
    }

#pragma unroll
    for (int i = 0; i < 8; i++) {
        float* crow = C + (size_t)(bm + ty * 8 + i) * N + bn + tx * 8;
#pragma unroll
        for (int q = 0; q < 2; q++) {
            float4 v = make_float4(acc[i][q * 4 + 0], acc[i][q * 4 + 1],
                                   acc[i][q * 4 + 2], acc[i][q * 4 + 3]);
            if (ACC) {
                float4 c = *(float4*)(crow + q * 4);
                v.x += c.x; v.y += c.y; v.z += c.z; v.w += c.w;
            }
            *(float4*)(crow + q * 4) = v;
        }
    }
}

// ---------------------------------------------------------------------------
// BatchNorm stats: per-feature mean + inv_std over T tokens (biased var).
// blockIdx.x in [0, 2*S): first S -> gate x, next S -> gate y.
// ---------------------------------------------------------------------------
__global__ void bn_stats_kernel(const float* __restrict__ gx,
                                const float* __restrict__ gy,
                                float* __restrict__ bn)
{
    int fb = blockIdx.x;
    const float* src = (fb < S_DIM) ? gx : gy;
    int f    = fb & (S_DIM - 1);
    int base = (fb < S_DIM) ? 0 : 2;

    float s = 0.f, s2 = 0.f;
    for (int r = threadIdx.x; r < T_TOK; r += 256) {
        float v = src[(size_t)r * S_DIM + f];
        s += v; s2 += v * v;
    }
    __shared__ float sh1[256], sh2[256];
    sh1[threadIdx.x] = s; sh2[threadIdx.x] = s2;
    __syncthreads();
    for (int st = 128; st > 0; st >>= 1) {
        if (threadIdx.x < st) {
            sh1[threadIdx.x] += sh1[threadIdx.x + st];
            sh2[threadIdx.x] += sh2[threadIdx.x + st];
        }
        __syncthreads();
    }
    if (threadIdx.x == 0) {
        float mean = sh1[0] / (float)T_TOK;
        float var  = sh2[0] / (float)T_TOK - mean * mean;
        bn[base * S_DIM + f]       = mean;
        bn[(base + 1) * S_DIM + f] = rsqrtf(var + 1e-5f);
    }
}

// ---------------------------------------------------------------------------
// Router: batchnorm-normalize -> log_softmax (x,y) -> top-16 of each ->
// top-16 of the 256 candidate sums. Candidate restriction is exact:
// top-k of a_i + b_j always lies in (top-k of a) x (top-k of b).
// One block (128 threads) per token.
// ---------------------------------------------------------------------------
#define NEG_BIG (-1e30f)

__global__ void __launch_bounds__(128)
router_kernel(const float* __restrict__ gx, const float* __restrict__ gy,
              const float* __restrict__ bn,
              int* __restrict__ ti, float* __restrict__ tw)
{
    const int t = blockIdx.x;
    const int f = threadIdx.x;

    __shared__ float lx[S_DIM], ly[S_DIM];
    __shared__ float rv[S_DIM];
    __shared__ int   ri[S_DIM];
    __shared__ float red[S_DIM];
    __shared__ float tvx[TOPK], tvy[TOPK];
    __shared__ int   tix[TOPK], tiy[TOPK];
    __shared__ float cand[2 * S_DIM];

    float vx = (gx[(size_t)t * S_DIM + f] - bn[f]) * bn[S_DIM + f];
    float vy = (gy[(size_t)t * S_DIM + f] - bn[2 * S_DIM + f]) * bn[3 * S_DIM + f];

    // log_softmax x
    red[f] = vx; __syncthreads();
    for (int s = 64; s > 0; s >>= 1) {
        if (f < s) red[f] = fmaxf(red[f], red[f + s]);
        __syncthreads();
    }
    float mx = red[0]; __syncthreads();
    red[f] = expf(vx - mx); __syncthreads();
    for (int s = 64; s > 0; s >>= 1) {
        if (f < s) red[f] += red[f + s];
        __syncthreads();
    }
    float lsx = mx + logf(red[0]); __syncthreads();
    lx[f] = vx - lsx;

    // log_softmax y
    red[f] = vy; __syncthreads();
    for (int s = 64; s > 0; s >>= 1) {
        if (f < s) red[f] = fmaxf(red[f], red[f + s]);
        __syncthreads();
    }
    float my = red[0]; __syncthreads();
    red[f] = expf(vy - my); __syncthreads();
    for (int s = 64; s > 0; s >>= 1) {
        if (f < s) red[f] += red[f + s];
        __syncthreads();
    }
    float lsy = my + logf(red[0]); __syncthreads();
    ly[f] = vy - lsy;
    __syncthreads();

    // top-16 of lx (iterative argmax; destroys lx)
    for (int r = 0; r < TOPK; r++) {
        rv[f] = lx[f]; ri[f] = f; __syncthreads();
        for (int s = 64; s > 0; s >>= 1) {
            if (f < s && rv[f + s] > rv[f]) { rv[f] = rv[f + s]; ri[f] = ri[f + s]; }
            __syncthreads();
        }
        if (f == 0) { tvx[r] = rv[0]; tix[r] = ri[0]; lx[ri[0]] = NEG_BIG; }
        __syncthreads();
    }
    // top-16 of ly
    for (int r = 0; r < TOPK; r++) {
        rv[f] = ly[f]; ri[f] = f; __syncthreads();
        for (int s = 64; s > 0; s >>= 1) {
            if (f < s && rv[f + s] > rv[f]) { rv[f] = rv[f + s]; ri[f] = ri[f + s]; }
            __syncthreads();
        }
        if (f == 0) { tvy[r] = rv[0]; tiy[r] = ri[0]; ly[ri[0]] = NEG_BIG; }
        __syncthreads();
    }

    // 256 candidates: c = a*16 + b  ->  tvx[a] + tvy[b]
    cand[f]       = tvx[f >> 4]         + tvy[f & 15];
    cand[f + 128] = tvx[(f + 128) >> 4] + tvy[f & 15];
    __syncthreads();

    for (int r = 0; r < TOPK; r++) {
        float v0 = cand[f], v1 = cand[f + 128];
        if (v1 > v0) { rv[f] = v1; ri[f] = f + 128; }
        else         { rv[f] = v0; ri[f] = f; }
        __syncthreads();
        for (int s = 64; s > 0; s >>= 1) {
            if (f < s && rv[f + s] > rv[f]) { rv[f] = rv[f + s]; ri[f] = ri[f + s]; }
            __syncthreads();
        }
        if (f == 0) {
            int c  = ri[0];
            int ai = c >> 4, bi = c & 15;
            ti[t * TOPK + r] = tix[ai] * S_DIM + tiy[bi];
            tw[t * TOPK + r] = expf(rv[0]);
            cand[c] = NEG_BIG;
        }
        __syncthreads();
    }
}

// ---------------------------------------------------------------------------
// Expert branch: out[t] = sum_k (w_k * dot(up_embed[e_k], x_t)) * down_embed[e_k]
// One block (256 threads) per token; x row cached in smem as float4.
// Writes the full output row (experts_states); MLP GEMM then accumulates.
// ---------------------------------------------------------------------------
__global__ void __launch_bounds__(256)
expert_kernel(const float* __restrict__ x,
              const float* __restrict__ up_embed,
              const float* __restrict__ down_embed,
              const int* __restrict__ ti, const float* __restrict__ tw,
              float* __restrict__ out)
{
    const int t   = blockIdx.x;
    const int tid = threadIdx.x;

    __shared__ float4 xs[H_DIM / 4];
    __shared__ float  red[256];
    __shared__ float  sc;

    xs[tid] = ((const float4*)(x + (size_t)t * H_DIM))[tid];
    __syncthreads();

    float4 acc = make_float4(0.f, 0.f, 0.f, 0.f);
    const float4 xv = xs[tid];

#pragma unroll 1
    for (int k = 0; k < TOPK; k++) {
        int e = ti[t * TOPK + k];
        float4 u = ((const float4*)(up_embed + (size_t)e * H_DIM))[tid];
        float p = u.x * xv.x + u.y * xv.y + u.z * xv.z + u.w * xv.w;

        red[tid] = p; __syncthreads();
        if (tid < 128) red[tid] += red[tid + 128]; __syncthreads();
        if (tid < 64)  red[tid] += red[tid + 64];  __syncthreads();
        if (tid < 32) {
            float v = red[tid] + red[tid + 32];
#pragma unroll
            for (int off = 16; off > 0; off >>= 1)
                v += __shfl_down_sync(0xffffffffu, v, off);
            if (tid == 0) sc = v;
        }
        __syncthreads();

        float coef = tw[t * TOPK + k] * sc;
        float4 d = ((const float4*)(down_embed + (size_t)e * H_DIM))[tid];
        acc.x += coef * d.x; acc.y += coef * d.y;
        acc.z += coef * d.z; acc.w += coef * d.w;
        __syncthreads();  // guard red reuse next iteration
    }
    ((float4*)(out + (size_t)t * H_DIM))[tid] = acc;
}

// ---------------------------------------------------------------------------
// h = silu(g) * u  (elementwise, in place on g)
// ---------------------------------------------------------------------------
__global__ void silu_mul_kernel(float* __restrict__ g, const float* __restrict__ u,
                                size_t n4)
{
    float4* g4 = (float4*)g;
    const float4* u4 = (const float4*)u;
    for (size_t i = (size_t)blockIdx.x * blockDim.x + threadIdx.x; i < n4;
         i += (size_t)gridDim.x * blockDim.x) {
        float4 a = g4[i];
        float4 b = u4[i];
        a.x = a.x / (1.f + expf(-a.x)) * b.x;
        a.y = a.y / (1.f + expf(-a.y)) * b.y;
        a.z = a.z / (1.f + expf(-a.z)) * b.z;
        a.w = a.w / (1.f + expf(-a.w)) * b.w;
        g4[i] = a;
    }
}

// ---------------------------------------------------------------------------
// Launch sequence (single stream, graph-capturable, allocation-free)
// ---------------------------------------------------------------------------
extern "C" void kernel_launch(void* const* d_in, const int* in_sizes, int n_in,
                              void* d_out, int out_size)
{
    const float* x   = (const float*)d_in[0];
    const float* wg  = (const float*)d_in[1];
    const float* wu  = (const float*)d_in[2];
    const float* wd  = (const float*)d_in[3];
    const float* wrx = (const float*)d_in[4];
    const float* wry = (const float*)d_in[5];
    const float* ue  = (const float*)d_in[6];
    const float* de  = (const float*)d_in[7];
    float* out = (float*)d_out;

    float *h1, *h2, *gx, *gy, *bn, *tw;
    int* ti;
    cudaGetSymbolAddress((void**)&h1, g_h1);
    cudaGetSymbolAddress((void**)&h2, g_h2);
    cudaGetSymbolAddress((void**)&gx, g_gx);
    cudaGetSymbolAddress((void**)&gy, g_gy);
    cudaGetSymbolAddress((void**)&bn, g_bn);
    cudaGetSymbolAddress((void**)&ti, g_ti);
    cudaGetSymbolAddress((void**)&tw, g_tw);

    // Router gate GEMMs: [T,H] @ [S,H]^T
    gemm_nt<false><<<dim3(S_DIM / BN, T_TOK / BM), 256>>>(x, wrx, gx, T_TOK, S_DIM, H_DIM);
    gemm_nt<false><<<dim3(S_DIM / BN, T_TOK / BM), 256>>>(x, wry, gy, T_TOK, S_DIM, H_DIM);

    // BatchNorm stats + routing top-k
    bn_stats_kernel<<<2 * S_DIM, 256>>>(gx, gy, bn);
    router_kernel<<<T_TOK, 128>>>(gx, gy, bn, ti, tw);

    // Expert branch writes out = experts_states
    expert_kernel<<<T_TOK, 256>>>(x, ue, de, ti, tw, out);

    // Dense MLP
    gemm_nt<false><<<dim3(I_DIM / BN, T_TOK / BM), 256>>>(x, wg, h1, T_TOK, I_DIM, H_DIM);
    gemm_nt<false><<<dim3(I_DIM / BN, T_TOK / BM), 256>>>(x, wu, h2, T_TOK, I_DIM, H_DIM);
    silu_mul_kernel<<<4096, 256>>>(h1, h2, (size_t)T_TOK * I_DIM / 4);

    // out += h @ Wd^T
    gemm_nt<true><<<dim3(H_DIM / BN, T_TOK / BM), 256>>>(h1, wd, out, T_TOK, H_DIM, I_DIM);
}

// round 4
// speedup vs baseline: 1.8972x; 1.8972x over previous
#include <cuda_runtime.h>
#include <cuda_bf16.h>
#include <math.h>
#include <stdint.h>

#define T_TOK 8192
#define H_DIM 1024
#define I_DIM 4096
#define S_DIM 128
#define TOPK  16
typedef __nv_bfloat16 bf16;

// ---------------- scratch ----------------
__device__ __align__(16) bf16  g_xh [(size_t)T_TOK * H_DIM];
__device__ __align__(16) bf16  g_xl [(size_t)T_TOK * H_DIM];
__device__ __align__(16) bf16  g_wgh[(size_t)I_DIM * H_DIM];
__device__ __align__(16) bf16  g_wgl[(size_t)I_DIM * H_DIM];
__device__ __align__(16) bf16  g_wuh[(size_t)I_DIM * H_DIM];
__device__ __align__(16) bf16  g_wul[(size_t)I_DIM * H_DIM];
__device__ __align__(16) bf16  g_wdh[(size_t)H_DIM * I_DIM];
__device__ __align__(16) bf16  g_wdl[(size_t)H_DIM * I_DIM];
__device__ __align__(16) bf16  g_wrxh[(size_t)S_DIM * H_DIM];
__device__ __align__(16) bf16  g_wrxl[(size_t)S_DIM * H_DIM];
__device__ __align__(16) bf16  g_wryh[(size_t)S_DIM * H_DIM];
__device__ __align__(16) bf16  g_wryl[(size_t)S_DIM * H_DIM];
__device__ __align__(16) bf16  g_hh [(size_t)T_TOK * I_DIM];
__device__ __align__(16) bf16  g_hl [(size_t)T_TOK * I_DIM];
__device__ __align__(16) float g_g  [(size_t)T_TOK * I_DIM];
__device__ __align__(16) float g_gx [(size_t)T_TOK * S_DIM];
__device__ __align__(16) float g_gy [(size_t)T_TOK * S_DIM];
__device__ __align__(16) float g_bn [4 * S_DIM];
__device__ __align__(16) int   g_ti [(size_t)T_TOK * TOPK];
__device__ __align__(16) float g_tw [(size_t)T_TOK * TOPK];

// ---------------- PTX helpers (all sm_80-compatible) ----------------
__device__ __forceinline__ uint32_t s2u(const void* p) {
    uint32_t a;
    asm("{ .reg .u64 t; cvta.to.shared.u64 t, %1; cvt.u32.u64 %0, t; }" : "=r"(a) : "l"(p));
    return a;
}
__device__ __forceinline__ void cp16(uint32_t dst, const void* src) {
    asm volatile("cp.async.cg.shared.global [%0], [%1], 16;" :: "r"(dst), "l"(src));
}
#define CP_COMMIT() asm volatile("cp.async.commit_group;" ::: "memory")
#define CP_WAIT(N)  asm volatile("cp.async.wait_group %0;" :: "n"(N) : "memory")

__device__ __forceinline__ void ldm4(uint32_t* r, uint32_t addr) {
    asm volatile("ldmatrix.sync.aligned.m8n8.x4.shared.b16 {%0,%1,%2,%3}, [%4];"
                 : "=r"(r[0]), "=r"(r[1]), "=r"(r[2]), "=r"(r[3]) : "r"(addr));
}
__device__ __forceinline__ void mma16816(float* c, const uint32_t* a, uint32_t b0, uint32_t b1) {
    asm volatile("mma.sync.aligned.m16n8k16.row.col.f32.bf16.bf16.f32 "
                 "{%0,%1,%2,%3}, {%4,%5,%6,%7}, {%8,%9}, {%0,%1,%2,%3};"
                 : "+f"(c[0]), "+f"(c[1]), "+f"(c[2]), "+f"(c[3])
                 : "r"(a[0]), "r"(a[1]), "r"(a[2]), "r"(a[3]), "r"(b0), "r"(b1));
}

// smem tile layout: 128 rows x 32 bf16 (64B/row); chunk = 16B of 8 bf16.
// swizzle: chunk' = chunk ^ ((row>>1)&3)  -> conflict-free ldmatrix & stores.
__device__ __forceinline__ uint32_t tile_off(int row, int chunk) {
    return (uint32_t)row * 64u + (uint32_t)((chunk ^ ((row >> 1) & 3)) * 16);
}

// ---------------- fp32 -> bf16 hi/lo split ----------------
__global__ void split_kernel(const float4* __restrict__ in,
                             __nv_bfloat162* __restrict__ hi,
                             __nv_bfloat162* __restrict__ lo, int n4)
{
    for (int i = blockIdx.x * blockDim.x + threadIdx.x; i < n4; i += gridDim.x * blockDim.x) {
        float4 v = in[i];
        bf16 h0 = __float2bfloat16(v.x), h1 = __float2bfloat16(v.y);
        bf16 h2 = __float2bfloat16(v.z), h3 = __float2bfloat16(v.w);
        __nv_bfloat162 H0{h0, h1}, H1{h2, h3};
        __nv_bfloat162 L0{__float2bfloat16(v.x - __bfloat162float(h0)),
                          __float2bfloat16(v.y - __bfloat162float(h1))};
        __nv_bfloat162 L1{__float2bfloat16(v.z - __bfloat162float(h2)),
                          __float2bfloat16(v.w - __bfloat162float(h3))};
        hi[2 * i] = H0; hi[2 * i + 1] = H1;
        lo[2 * i] = L0; lo[2 * i + 1] = L1;
    }
}

// ---------------------------------------------------------------------------
// bf16x3 GEMM via mma.sync: C[M,N] = (Ah+Al)[M,K] @ ((Bh+Bl)[N,K])^T
// 128x128 tile, BK=32, 3-stage cp.async, 256 thr = 8 warps (4m x 2n),
// warp tile 32x64 (2 m16 x 8 n8 per warp).
// Pass sequence over k-chunks: (Ah,Bh), (Al,Bh), (Ah,Bl).
// EPI: 0 = C = D;  1 = h=silu(G)*D split -> (Hh,Hl);  2 = C += D
// ---------------------------------------------------------------------------
template<int EPI>
__global__ void __launch_bounds__(256, 2)
gemm_mma(const bf16* __restrict__ Ah, const bf16* __restrict__ Al,
         const bf16* __restrict__ Bh, const bf16* __restrict__ Bl,
         int K, int KC, int niter, int N,
         float* __restrict__ C, const float* __restrict__ G,
         bf16* __restrict__ Hh, bf16* __restrict__ Hl)
{
    constexpr uint32_t TILE = 128 * 64;      // 8 KB per operand tile
    constexpr uint32_t STAGE = 2 * TILE;     // A + B
    extern __shared__ char smem[];
    const uint32_t sbase = s2u(smem);

    const int tid  = threadIdx.x;
    const int lane = tid & 31;
    const int wid  = tid >> 5;
    const int wm   = wid >> 1;         // 0..3 -> m offset wm*32
    const int wn   = wid & 1;          // 0..1 -> n offset wn*64
    const int bm   = blockIdx.y * 128;
    const int bn   = blockIdx.x * 128;

    // producer mapping: thread covers (row = tid>>1, chunks c0,c0+1)
    const int prow = tid >> 1;
    const int pc0  = (tid & 1) * 2;
    const uint32_t pa_off0 = tile_off(prow, pc0);
    const uint32_t pa_off1 = tile_off(prow, pc0 + 1);

    // consumer ldmatrix offsets (within a tile, before stage base)
    const int lrow8 = ((lane >> 3) & 1) * 8 + (lane & 7);
    const int lchnk = lane >> 4;              // 0 or 1 -> k-chunk select
    uint32_t a_off[2], b_off[4];
#pragma unroll
    for (int mt = 0; mt < 2; mt++)
        a_off[mt] = tile_off(wm * 32 + mt * 16 + lrow8, lchnk);
#pragma unroll
    for (int p = 0; p < 4; p++)
        b_off[p] = tile_off(wn * 64 + p * 16 + lrow8, lchnk);

    float acc[2][8][4];
#pragma unroll
    for (int mt = 0; mt < 2; mt++)
#pragma unroll
        for (int nt = 0; nt < 8; nt++)
#pragma unroll
            for (int q = 0; q < 4; q++) acc[mt][nt][q] = 0.f;

    auto load_stage = [&](int j) {
        const int pass = j / KC;
        const int kk   = (j - pass * KC) * 32;
        const bf16* Ap = (pass == 1) ? Al : Ah;
        const bf16* Bp = (pass == 2) ? Bl : Bh;
        const uint32_t sa = sbase + (uint32_t)(j % 3) * STAGE;
        const uint32_t sb = sa + TILE;
        const bf16* ga = Ap + (size_t)(bm + prow) * K + kk + pc0 * 8;
        const bf16* gb = Bp + (size_t)(bn + prow) * K + kk + pc0 * 8;
        cp16(sa + pa_off0, ga);
        cp16(sa + pa_off1, ga + 8);
        cp16(sb + pa_off0, gb);
        cp16(sb + pa_off1, gb + 8);
    };

    // prologue: stages 0,1
    load_stage(0); CP_COMMIT();
    load_stage(1); CP_COMMIT();

    for (int j = 0; j < niter; ++j) {
        CP_WAIT(1);
        __syncthreads();
        if (j + 2 < niter) load_stage(j + 2);
        CP_COMMIT();

        const uint32_t sa = sbase + (uint32_t)(j % 3) * STAGE;
        const uint32_t sb = sa + TILE;
#pragma unroll
        for (int ks = 0; ks < 2; ks++) {
            const uint32_t koff = (uint32_t)(ks * 2) * 16;  // chunk advance: handled via +32B? no:
            // chunk index shift: base offsets were built with chunk=lchnk; for ks we need
            // chunk = ks*2 + lchnk. Swizzle XOR acts on chunk bits; since ks*2 flips bit1
            // of chunk and XOR mask ((row>>1)&3) is independent, adding ks*2 chunks is
            // equivalent to XOR-ing bit1 of the chunk field: offset ^ (ks ? 32 : 0).
            const uint32_t kx = ks ? 32u : 0u;
            uint32_t a[2][4], b[4][4];
#pragma unroll
            for (int mt = 0; mt < 2; mt++) ldm4(a[mt], sa + (a_off[mt] ^ kx));
#pragma unroll
            for (int p = 0; p < 4; p++)    ldm4(b[p], sb + (b_off[p] ^ kx));
#pragma unroll
            for (int mt = 0; mt < 2; mt++)
#pragma unroll
                for (int p = 0; p < 4; p++) {
                    mma16816(acc[mt][2 * p],     a[mt], b[p][0], b[p][2]);
                    mma16816(acc[mt][2 * p + 1], a[mt], b[p][1], b[p][3]);
                }
            (void)koff;
        }
    }

    // ---- epilogue (register accumulators -> global) ----
    const int gid  = lane >> 2;
    const int tid4 = lane & 3;
#pragma unroll
    for (int mt = 0; mt < 2; mt++) {
        const int r0 = bm + wm * 32 + mt * 16 + gid;
        const int r1 = r0 + 8;
#pragma unroll
        for (int nt = 0; nt < 8; nt++) {
            const int col = bn + wn * 64 + nt * 8 + tid4 * 2;
            float v00 = acc[mt][nt][0], v01 = acc[mt][nt][1];
            float v10 = acc[mt][nt][2], v11 = acc[mt][nt][3];
            if (EPI == 0) {
                *(float2*)(C + (size_t)r0 * N + col) = make_float2(v00, v01);
                *(float2*)(C + (size_t)r1 * N + col) = make_float2(v10, v11);
            } else if (EPI == 2) {
                float2 c0 = *(float2*)(C + (size_t)r0 * N + col);
                float2 c1 = *(float2*)(C + (size_t)r1 * N + col);
                *(float2*)(C + (size_t)r0 * N + col) = make_float2(c0.x + v00, c0.y + v01);
                *(float2*)(C + (size_t)r1 * N + col) = make_float2(c1.x + v10, c1.y + v11);
            } else {
                float2 g0 = *(const float2*)(G + (size_t)r0 * N + col);
                float2 g1 = *(const float2*)(G + (size_t)r1 * N + col);
                float h00 = g0.x / (1.f + expf(-g0.x)) * v00;
                float h01 = g0.y / (1.f + expf(-g0.y)) * v01;
                float h10 = g1.x / (1.f + expf(-g1.x)) * v10;
                float h11 = g1.y / (1.f + expf(-g1.y)) * v11;
                bf16 b00 = __float2bfloat16(h00), b01 = __float2bfloat16(h01);
                bf16 b10 = __float2bfloat16(h10), b11 = __float2bfloat16(h11);
                *(__nv_bfloat162*)(Hh + (size_t)r0 * N + col) = __nv_bfloat162{b00, b01};
                *(__nv_bfloat162*)(Hh + (size_t)r1 * N + col) = __nv_bfloat162{b10, b11};
                *(__nv_bfloat162*)(Hl + (size_t)r0 * N + col) =
                    __nv_bfloat162{__float2bfloat16(h00 - __bfloat162float(b00)),
                                   __float2bfloat16(h01 - __bfloat162float(b01))};
                *(__nv_bfloat162*)(Hl + (size_t)r1 * N + col) =
                    __nv_bfloat162{__float2bfloat16(h10 - __bfloat162float(b10)),
                                   __float2bfloat16(h11 - __bfloat162float(b11))};
            }
        }
    }
}

// ---------------- BatchNorm stats ----------------
__global__ void bn_stats_kernel(const float* __restrict__ gx,
                                const float* __restrict__ gy, float* __restrict__ bn)
{
    int fb = blockIdx.x;
    const float* src = (fb < S_DIM) ? gx : gy;
    int f = fb & (S_DIM - 1), base = (fb < S_DIM) ? 0 : 2;
    float s = 0.f, s2 = 0.f;
    for (int r = threadIdx.x; r < T_TOK; r += 256) {
        float v = src[(size_t)r * S_DIM + f];
        s += v; s2 += v * v;
    }
    __shared__ float sh1[256], sh2[256];
    sh1[threadIdx.x] = s; sh2[threadIdx.x] = s2;
    __syncthreads();
    for (int st = 128; st > 0; st >>= 1) {
        if (threadIdx.x < st) { sh1[threadIdx.x] += sh1[threadIdx.x + st]; sh2[threadIdx.x] += sh2[threadIdx.x + st]; }
        __syncthreads();
    }
    if (threadIdx.x == 0) {
        float mean = sh1[0] / (float)T_TOK;
        float var  = sh2[0] / (float)T_TOK - mean * mean;
        bn[base * S_DIM + f] = mean;
        bn[(base + 1) * S_DIM + f] = rsqrtf(var + 1e-5f);
    }
}

// ---------------- Router ----------------
#define NEG_BIG (-1e30f)
__global__ void __launch_bounds__(128)
router_kernel(const float* __restrict__ gx, const float* __restrict__ gy,
              const float* __restrict__ bn, int* __restrict__ ti, float* __restrict__ tw)
{
    const int t = blockIdx.x, f = threadIdx.x;
    __shared__ float lx[S_DIM], ly[S_DIM], rv[S_DIM], red[S_DIM];
    __shared__ int   ri[S_DIM];
    __shared__ float tvx[TOPK], tvy[TOPK];
    __shared__ int   tix[TOPK], tiy[TOPK];
    __shared__ float cand[2 * S_DIM];

    float vx = (gx[(size_t)t * S_DIM + f] - bn[f]) * bn[S_DIM + f];
    float vy = (gy[(size_t)t * S_DIM + f] - bn[2 * S_DIM + f]) * bn[3 * S_DIM + f];

    red[f] = vx; __syncthreads();
    for (int s = 64; s > 0; s >>= 1) { if (f < s) red[f] = fmaxf(red[f], red[f + s]); __syncthreads(); }
    float mx = red[0]; __syncthreads();
    red[f] = expf(vx - mx); __syncthreads();
    for (int s = 64; s > 0; s >>= 1) { if (f < s) red[f] += red[f + s]; __syncthreads(); }
    float lsx = mx + logf(red[0]); __syncthreads();
    lx[f] = vx - lsx;

    red[f] = vy; __syncthreads();
    for (int s = 64; s > 0; s >>= 1) { if (f < s) red[f] = fmaxf(red[f], red[f + s]); __syncthreads(); }
    float my = red[0]; __syncthreads();
    red[f] = expf(vy - my); __syncthreads();
    for (int s = 64; s > 0; s >>= 1) { if (f < s) red[f] += red[f + s]; __syncthreads(); }
    float lsy = my + logf(red[0]); __syncthreads();
    ly[f] = vy - lsy;
    __syncthreads();

    for (int r = 0; r < TOPK; r++) {
        rv[f] = lx[f]; ri[f] = f; __syncthreads();
        for (int s = 64; s > 0; s >>= 1) {
            if (f < s && rv[f + s] > rv[f]) { rv[f] = rv[f + s]; ri[f] = ri[f + s]; }
            __syncthreads();
        }
        if (f == 0) { tvx[r] = rv[0]; tix[r] = ri[0]; lx[ri[0]] = NEG_BIG; }
        __syncthreads();
    }
    for (int r = 0; r < TOPK; r++) {
        rv[f] = ly[f]; ri[f] = f; __syncthreads();
        for (int s = 64; s > 0; s >>= 1) {
            if (f < s && rv[f + s] > rv[f]) { rv[f] = rv[f + s]; ri[f] = ri[f + s]; }
            __syncthreads();
        }
        if (f == 0) { tvy[r] = rv[0]; tiy[r] = ri[0]; ly[ri[0]] = NEG_BIG; }
        __syncthreads();
    }

    cand[f]       = tvx[f >> 4]         + tvy[f & 15];
    cand[f + 128] = tvx[(f + 128) >> 4] + tvy[f & 15];
    __syncthreads();

    for (int r = 0; r < TOPK; r++) {
        float v0 = cand[f], v1 = cand[f + 128];
        if (v1 > v0) { rv[f] = v1; ri[f] = f + 128; } else { rv[f] = v0; ri[f] = f; }
        __syncthreads();
        for (int s = 64; s > 0; s >>= 1) {
            if (f < s && rv[f + s] > rv[f]) { rv[f] = rv[f + s]; ri[f] = ri[f + s]; }
            __syncthreads();
        }
        if (f == 0) {
            int c = ri[0], ai = c >> 4, bi = c & 15;
            ti[t * TOPK + r] = tix[ai] * S_DIM + tiy[bi];
            tw[t * TOPK + r] = expf(rv[0]);
            cand[c] = NEG_BIG;
        }
        __syncthreads();
    }
}

// ---------------- Expert branch ----------------
__global__ void __launch_bounds__(256)
expert_kernel(const float* __restrict__ x, const float* __restrict__ up_embed,
              const float* __restrict__ down_embed,
              const int* __restrict__ ti, const float* __restrict__ tw,
              float* __restrict__ out)
{
    const int t = blockIdx.x, tid = threadIdx.x;
    __shared__ float4 xs[H_DIM / 4];
    __shared__ float  red[256];
    __shared__ float  sc;

    xs[tid] = ((const float4*)(x + (size_t)t * H_DIM))[tid];
    __syncthreads();
    float4 acc = make_float4(0.f, 0.f, 0.f, 0.f);
    const float4 xv = xs[tid];

#pragma unroll 1
    for (int k = 0; k < TOPK; k++) {
        int e = ti[t * TOPK + k];
        float4 u = ((const float4*)(up_embed + (size_t)e * H_DIM))[tid];
        float p = u.x * xv.x + u.y * xv.y + u.z * xv.z + u.w * xv.w;
        red[tid] = p; __syncthreads();
        if (tid < 128) red[tid] += red[tid + 128]; __syncthreads();
        if (tid < 64)  red[tid] += red[tid + 64];  __syncthreads();
        if (tid < 32) {
            float v = red[tid] + red[tid + 32];
#pragma unroll
            for (int off = 16; off > 0; off >>= 1) v += __shfl_down_sync(0xffffffffu, v, off);
            if (tid == 0) sc = v;
        }
        __syncthreads();
        float coef = tw[t * TOPK + k] * sc;
        float4 d = ((const float4*)(down_embed + (size_t)e * H_DIM))[tid];
        acc.x += coef * d.x; acc.y += coef * d.y; acc.z += coef * d.z; acc.w += coef * d.w;
        __syncthreads();
    }
    ((float4*)(out + (size_t)t * H_DIM))[tid] = acc;
}

// ---------------- launch ----------------
extern "C" void kernel_launch(void* const* d_in, const int* in_sizes, int n_in,
                              void* d_out, int out_size)
{
    const float* x   = (const float*)d_in[0];
    const float* wg  = (const float*)d_in[1];
    const float* wu  = (const float*)d_in[2];
    const float* wd  = (const float*)d_in[3];
    const float* wrx = (const float*)d_in[4];
    const float* wry = (const float*)d_in[5];
    const float* ue  = (const float*)d_in[6];
    const float* de  = (const float*)d_in[7];
    float* out = (float*)d_out;

    bf16 *xh, *xl, *wgh, *wgl, *wuh, *wul, *wdh, *wdl, *wrxh, *wrxl, *wryh, *wryl, *hh, *hl;
    float *gg, *gx, *gy, *bn, *tw;
    int* ti;
    cudaGetSymbolAddress((void**)&xh, g_xh);   cudaGetSymbolAddress((void**)&xl, g_xl);
    cudaGetSymbolAddress((void**)&wgh, g_wgh); cudaGetSymbolAddress((void**)&wgl, g_wgl);
    cudaGetSymbolAddress((void**)&wuh, g_wuh); cudaGetSymbolAddress((void**)&wul, g_wul);
    cudaGetSymbolAddress((void**)&wdh, g_wdh); cudaGetSymbolAddress((void**)&wdl, g_wdl);
    cudaGetSymbolAddress((void**)&wrxh, g_wrxh); cudaGetSymbolAddress((void**)&wrxl, g_wrxl);
    cudaGetSymbolAddress((void**)&wryh, g_wryh); cudaGetSymbolAddress((void**)&wryl, g_wryl);
    cudaGetSymbolAddress((void**)&hh, g_hh);   cudaGetSymbolAddress((void**)&hl, g_hl);
    cudaGetSymbolAddress((void**)&gg, g_g);
    cudaGetSymbolAddress((void**)&gx, g_gx);   cudaGetSymbolAddress((void**)&gy, g_gy);
    cudaGetSymbolAddress((void**)&bn, g_bn);
    cudaGetSymbolAddress((void**)&ti, g_ti);   cudaGetSymbolAddress((void**)&tw, g_tw);

    constexpr int SMEM = 3 * 2 * 128 * 64;  // 49152 bytes (3 stages x (A+B))

    // splits
    split_kernel<<<2048, 256>>>((const float4*)x, (__nv_bfloat162*)xh, (__nv_bfloat162*)xl, T_TOK * H_DIM / 4);
    split_kernel<<<2048, 256>>>((const float4*)wg, (__nv_bfloat162*)wgh, (__nv_bfloat162*)wgl, I_DIM * H_DIM / 4);
    split_kernel<<<2048, 256>>>((const float4*)wu, (__nv_bfloat162*)wuh, (__nv_bfloat162*)wul, I_DIM * H_DIM / 4);
    split_kernel<<<2048, 256>>>((const float4*)wd, (__nv_bfloat162*)wdh, (__nv_bfloat162*)wdl, H_DIM * I_DIM / 4);
    split_kernel<<<128, 256>>>((const float4*)wrx, (__nv_bfloat162*)wrxh, (__nv_bfloat162*)wrxl, S_DIM * H_DIM / 4);
    split_kernel<<<128, 256>>>((const float4*)wry, (__nv_bfloat162*)wryh, (__nv_bfloat162*)wryl, S_DIM * H_DIM / 4);

    // router gates: [T,128] = x @ Wr^T   (K=1024 -> KC=32, niter=96)
    gemm_mma<0><<<dim3(1, T_TOK / 128), 256, SMEM>>>(
        xh, xl, wrxh, wrxl, H_DIM, H_DIM / 32, 3 * H_DIM / 32, S_DIM, gx, nullptr, nullptr, nullptr);
    gemm_mma<0><<<dim3(1, T_TOK / 128), 256, SMEM>>>(
        xh, xl, wryh, wryl, H_DIM, H_DIM / 32, 3 * H_DIM / 32, S_DIM, gy, nullptr, nullptr, nullptr);

    bn_stats_kernel<<<2 * S_DIM, 256>>>(gx, gy, bn);
    router_kernel<<<T_TOK, 128>>>(gx, gy, bn, ti, tw);
    expert_kernel<<<T_TOK, 256>>>(x, ue, de, ti, tw, out);

    // gate = x @ Wg^T
    gemm_mma<0><<<dim3(I_DIM / 128, T_TOK / 128), 256, SMEM>>>(
        xh, xl, wgh, wgl, H_DIM, H_DIM / 32, 3 * H_DIM / 32, I_DIM, gg, nullptr, nullptr, nullptr);
    // up = x @ Wu^T; epilogue: h = silu(gate)*up -> split (hh, hl)
    gemm_mma<1><<<dim3(I_DIM / 128, T_TOK / 128), 256, SMEM>>>(
        xh, xl, wuh, wul, H_DIM, H_DIM / 32, 3 * H_DIM / 32, I_DIM, nullptr, gg, hh, hl);
    // out += h @ Wd^T   (K=4096 -> KC=128, niter=384)
    gemm_mma<2><<<dim3(H_DIM / 128, T_TOK / 128), 256, SMEM>>>(
        hh, hl, wdh, wdl, I_DIM, I_DIM / 32, 3 * I_DIM / 32, H_DIM, out, nullptr, nullptr, nullptr);
}